// round 17
// baseline (speedup 1.0000x reference)
#include <cuda_runtime.h>
#include <cuda_bf16.h>
#include <cstdint>

typedef unsigned long long ull;

constexpr int kB = 64;      // batch
constexpr int kT = 256;     // time
constexpr int kH = 512;     // hidden
constexpr int kG = 2048;    // 4*H gate cols
constexpr int kM = kB * kT; // 16384 GEMM rows
constexpr int kCG = 32;     // column groups (16 hidden units each)
constexpr int kBG = 4;      // batch groups (16 batch elements each)
constexpr int kGrpCTA = kCG;
constexpr int kQRow = 264;                     // hi 128 | lo 128 | pad 8 (528B)
constexpr int kQBytes = 16 * kQRow * 2;        // 8448 per quarter tile

// ---------------- scratch ----------------------------------------------------
__device__ float  g_G[(size_t)kM * kG];            // input projections (128 MB)
__device__ __nv_bfloat16 g_As[(size_t)kM * 1024];  // A split hi|lo (32 MB)
__device__ __nv_bfloat16 g_WiTh[(size_t)kG * kH];  // Wi hi, transposed [N,K]
__device__ __nv_bfloat16 g_WiTl[(size_t)kG * kH];  // Wi lo
__device__ __nv_bfloat16 g_WhTh[(size_t)kG * kH];  // Wh hi, transposed [N,K]
__device__ __nv_bfloat16 g_WhTl[(size_t)kG * kH];  // Wh lo
// h exchange: [pingpong][k-quarter][batch][row(hi128|lo128|pad8)]
__device__ __align__(256) __nv_bfloat16 g_hbf4[2][4][kB][kQRow];
__device__ int g_cnt[kBG * 32];                    // initial barrier
__device__ int g_flg[kBG * 32];
__device__ int g_hflag[kBG][32 * 32];              // per-producer step flags

// ---------------- helpers -----------------------------------------------------
__device__ __forceinline__ float tanh_hw(float x) {
    float t;
    asm("tanh.approx.f32 %0, %1;" : "=f"(t) : "f"(x));
    return t;
}
__device__ __forceinline__ float sigf(float x) {
    return fmaf(tanh_hw(0.5f * x), 0.5f, 0.5f);
}

__device__ __forceinline__ void mma_bf16(float* c, const uint32_t* a,
                                         const uint32_t* b) {
    asm volatile(
        "mma.sync.aligned.m16n8k16.row.col.f32.bf16.bf16.f32 "
        "{%0,%1,%2,%3}, {%4,%5,%6,%7}, {%8,%9}, {%0,%1,%2,%3};"
        : "+f"(c[0]), "+f"(c[1]), "+f"(c[2]), "+f"(c[3])
        : "r"(a[0]), "r"(a[1]), "r"(a[2]), "r"(a[3]), "r"(b[0]), "r"(b[1]));
}
__device__ __forceinline__ void ldmx4(uint32_t* r, uint32_t addr) {
    asm volatile("ldmatrix.sync.aligned.m8n8.x4.shared.b16 {%0,%1,%2,%3}, [%4];"
                 : "=r"(r[0]), "=r"(r[1]), "=r"(r[2]), "=r"(r[3]) : "r"(addr));
}
__device__ __forceinline__ void ldmx2(uint32_t* r, uint32_t addr) {
    asm volatile("ldmatrix.sync.aligned.m8n8.x2.shared.b16 {%0,%1}, [%2];"
                 : "=r"(r[0]), "=r"(r[1]) : "r"(addr));
}
__device__ __forceinline__ uint32_t smem_u32(const void* p) {
    uint32_t a;
    asm("{ .reg .u64 t; cvta.to.shared.u64 t, %1; cvt.u32.u64 %0, t; }"
        : "=r"(a) : "l"(p));
    return a;
}
__device__ __forceinline__ void mbar_init(uint32_t a, uint32_t cnt) {
    asm volatile("mbarrier.init.shared.b64 [%0], %1;" :: "r"(a), "r"(cnt) : "memory");
}
__device__ __forceinline__ void mbar_wait(uint32_t a, uint32_t parity) {
    asm volatile(
        "{\n\t.reg .pred P;\n\t"
        "WL_%=:\n\t"
        "mbarrier.try_wait.parity.acquire.cta.shared::cta.b64 P, [%0], %1, 0x989680;\n\t"
        "@P bra.uni WD_%=;\n\t"
        "bra.uni WL_%=;\n\t"
        "WD_%=:\n\t}"
        :: "r"(a), "r"(parity) : "memory");
}
__device__ __forceinline__ void bulk_g2s(uint32_t dst, const void* src,
                                         uint32_t bytes, uint32_t mbar) {
    asm volatile(
        "cp.async.bulk.shared::cluster.global.mbarrier::complete_tx::bytes "
        "[%0], [%1], %2, [%3];"
        :: "r"(dst), "l"(src), "r"(bytes), "r"(mbar) : "memory");
}
__device__ __forceinline__ void mbar_expect(uint32_t mbar, uint32_t bytes) {
    asm volatile("mbarrier.arrive.expect_tx.shared.b64 _, [%0], %1;"
                 :: "r"(mbar), "r"(bytes) : "memory");
}

// ---------------- split/prep kernels -------------------------------------------
__global__ void __launch_bounds__(256)
split_x(const float* __restrict__ X)
{
    if (blockIdx.x == 0) {
        if (threadIdx.x < kBG) {
            g_cnt[threadIdx.x * 32] = 0;
            g_flg[threadIdx.x * 32] = 0;
        }
        for (int i = threadIdx.x; i < kBG * 32 * 32; i += 256)
            ((int*)g_hflag)[i] = 0;
    }
    size_t i = ((size_t)blockIdx.x * 256 + threadIdx.x) * 4;
    float4 v = *(const float4*)(X + i);
    size_t m = i >> 9;
    int k = (int)(i & 511);
    __nv_bfloat16 h0 = __float2bfloat16_rn(v.x);
    __nv_bfloat16 h1 = __float2bfloat16_rn(v.y);
    __nv_bfloat16 h2 = __float2bfloat16_rn(v.z);
    __nv_bfloat16 h3 = __float2bfloat16_rn(v.w);
    __nv_bfloat16 l0 = __float2bfloat16_rn(v.x - __bfloat162float(h0));
    __nv_bfloat16 l1 = __float2bfloat16_rn(v.y - __bfloat162float(h1));
    __nv_bfloat16 l2 = __float2bfloat16_rn(v.z - __bfloat162float(h2));
    __nv_bfloat16 l3 = __float2bfloat16_rn(v.w - __bfloat162float(h3));
    __nv_bfloat16* ph = g_As + m * 1024 + k;
    __nv_bfloat16* pl = ph + 512;
    *(__nv_bfloat162*)(ph)     = __nv_bfloat162(h0, h1);
    *(__nv_bfloat162*)(ph + 2) = __nv_bfloat162(h2, h3);
    *(__nv_bfloat162*)(pl)     = __nv_bfloat162(l0, l1);
    *(__nv_bfloat162*)(pl + 2) = __nv_bfloat162(l2, l3);
}

__global__ void __launch_bounds__(256)
split_pair(const float* __restrict__ W, __nv_bfloat16* __restrict__ dH,
           __nv_bfloat16* __restrict__ dL)
{
    __shared__ float tile[32][33];
    const int tx = threadIdx.x & 31;
    const int ty = threadIdx.x >> 5;
    const int n0 = blockIdx.x * 32;
    const int k0 = blockIdx.y * 32;
#pragma unroll
    for (int j = 0; j < 4; j++)
        tile[ty + j * 8][tx] = W[(size_t)(k0 + ty + j * 8) * kG + n0 + tx];
    __syncthreads();
#pragma unroll
    for (int j = 0; j < 4; j++) {
        const int n = n0 + ty + j * 8;
        const int k = k0 + tx;
        const float v = tile[tx][ty + j * 8];
        __nv_bfloat16 hi = __float2bfloat16_rn(v);
        __nv_bfloat16 lo = __float2bfloat16_rn(v - __bfloat162float(hi));
        dH[(size_t)n * kH + k] = hi;
        dL[(size_t)n * kH + k] = lo;
    }
}

// ---------------- HMMA input-projection GEMM: 128x256 CTA, 64x64 warp tiles ----
constexpr int kLds = 40;                       // padded row (bf16), 80B stride
constexpr int kASz = 128 * kLds;               // per A tile (elems)
constexpr int kBSz = 256 * kLds;               // per B tile (elems)
constexpr int kGemmSmem = (2 * kASz + 2 * kBSz) * 2;  // 61440 B

extern __shared__ __align__(16) __nv_bfloat16 g_sm[];

__global__ void __launch_bounds__(256, 1)
gemm_mma(const float* __restrict__ bi, const float* __restrict__ bh,
         float* __restrict__ C)
{
    __nv_bfloat16* Ah = g_sm;
    __nv_bfloat16* Al = Ah + kASz;
    __nv_bfloat16* Bh = Al + kASz;
    __nv_bfloat16* Bl = Bh + kBSz;

    const int tid  = threadIdx.x;
    const int wid  = tid >> 5;
    const int lane = tid & 31;
    const int g    = lane >> 2;
    const int tig  = lane & 3;
    const int n0 = blockIdx.x * 256;
    const int m0 = blockIdx.y * 128;
    const int wm = (wid >> 2) * 64;     // 2 m-slices
    const int wn = (wid & 3) * 64;      // 4 n-slices

    const int lr = tid >> 1;            // A staging row
    const int lh = tid & 1;             // A staging half (16 elems)

    // fragment lane addressing
    const int lrow = ((lane >> 3) & 1) * 8 + (lane & 7);
    const int lcolB = (lane >> 4) * 16;
    const uint32_t aBaseH = smem_u32(Ah) + ((wm + lrow) * kLds) * 2 + lcolB;
    const uint32_t aBaseL = smem_u32(Al) + ((wm + lrow) * kLds) * 2 + lcolB;
    const int brow = wn + (lane & 7);
    const int bcolB = ((lane >> 3) & 1) * 16;
    const uint32_t bBaseH = smem_u32(Bh) + (brow * kLds) * 2 + bcolB;
    const uint32_t bBaseL = smem_u32(Bl) + (brow * kLds) * 2 + bcolB;

    float acc[4][8][4];
#pragma unroll
    for (int mf = 0; mf < 4; mf++)
#pragma unroll
        for (int nf = 0; nf < 8; nf++)
#pragma unroll
            for (int i = 0; i < 4; i++) acc[mf][nf][i] = 0.f;

    for (int kt = 0; kt < 16; kt++) {
        const int koff = kt * 32 + lh * 16;
        // A: 2 threads/row, 16 elems each
        const __nv_bfloat16* pa = g_As + (size_t)(m0 + lr) * 1024 + koff;
        const __nv_bfloat16* pl = pa + 512;
        uint4 vah0 = *(const uint4*)(pa);
        uint4 vah1 = *(const uint4*)(pa + 8);
        uint4 val0 = *(const uint4*)(pl);
        uint4 val1 = *(const uint4*)(pl + 8);
        // B: 1 thread/row, full 32 elems (4 uint4) per array
        const int kb = kt * 32;
        const __nv_bfloat16* pbh = g_WiTh + (size_t)(n0 + tid) * 512 + kb;
        const __nv_bfloat16* pbl = g_WiTl + (size_t)(n0 + tid) * 512 + kb;
        uint4 vbh0 = *(const uint4*)(pbh);
        uint4 vbh1 = *(const uint4*)(pbh + 8);
        uint4 vbh2 = *(const uint4*)(pbh + 16);
        uint4 vbh3 = *(const uint4*)(pbh + 24);
        uint4 vbl0 = *(const uint4*)(pbl);
        uint4 vbl1 = *(const uint4*)(pbl + 8);
        uint4 vbl2 = *(const uint4*)(pbl + 16);
        uint4 vbl3 = *(const uint4*)(pbl + 24);
        __syncthreads();
        __nv_bfloat16* da = Ah + lr * kLds + lh * 16;
        __nv_bfloat16* dl = Al + lr * kLds + lh * 16;
        *(uint4*)(da)     = vah0;
        *(uint4*)(da + 8) = vah1;
        *(uint4*)(dl)     = val0;
        *(uint4*)(dl + 8) = val1;
        __nv_bfloat16* db = Bh + tid * kLds;
        __nv_bfloat16* dc = Bl + tid * kLds;
        *(uint4*)(db)      = vbh0;
        *(uint4*)(db + 8)  = vbh1;
        *(uint4*)(db + 16) = vbh2;
        *(uint4*)(db + 24) = vbh3;
        *(uint4*)(dc)      = vbl0;
        *(uint4*)(dc + 8)  = vbl1;
        *(uint4*)(dc + 16) = vbl2;
        *(uint4*)(dc + 24) = vbl3;
        __syncthreads();

#pragma unroll
        for (int ks = 0; ks < 2; ks++) {
            const int kOff = ks * 32;   // bytes
            uint32_t bhf[8][2], blf[8][2];
#pragma unroll
            for (int nf = 0; nf < 8; nf++) {
                ldmx2(bhf[nf], bBaseH + nf * 8 * kLds * 2 + kOff);
                ldmx2(blf[nf], bBaseL + nf * 8 * kLds * 2 + kOff);
            }
#pragma unroll
            for (int mf = 0; mf < 4; mf++) {
                uint32_t ah[4], al[4];
                ldmx4(ah, aBaseH + mf * 16 * kLds * 2 + kOff);
                ldmx4(al, aBaseL + mf * 16 * kLds * 2 + kOff);
#pragma unroll
                for (int nf = 0; nf < 8; nf++) {
                    mma_bf16(acc[mf][nf], ah, bhf[nf]);
                    mma_bf16(acc[mf][nf], al, bhf[nf]);
                    mma_bf16(acc[mf][nf], ah, blf[nf]);
                }
            }
        }
    }

    // epilogue with fused bias
    float2 bias2[8];
#pragma unroll
    for (int nf = 0; nf < 8; nf++) {
        const int n = n0 + wn + nf * 8 + tig * 2;
        bias2[nf].x = __ldg(bi + n) + __ldg(bh + n);
        bias2[nf].y = __ldg(bi + n + 1) + __ldg(bh + n + 1);
    }
#pragma unroll
    for (int mf = 0; mf < 4; mf++) {
        const int m = m0 + wm + mf * 16 + g;
#pragma unroll
        for (int nf = 0; nf < 8; nf++) {
            const int n = n0 + wn + nf * 8 + tig * 2;
            float2 o0, o1;
            o0.x = acc[mf][nf][0] + bias2[nf].x;
            o0.y = acc[mf][nf][1] + bias2[nf].y;
            o1.x = acc[mf][nf][2] + bias2[nf].x;
            o1.y = acc[mf][nf][3] + bias2[nf].y;
            *(float2*)(C + (size_t)m * kG + n)       = o0;
            *(float2*)(C + (size_t)(m + 8) * kG + n) = o1;
        }
    }
}

// ---------------- initial group barrier (per launch) ----------------------------
__device__ __forceinline__ void gbar_rel(int idx, int tid, int bg)
{
    __syncthreads();
    if (tid == 0) {
        int* cnt = &g_cnt[bg * 32];
        int* flg = &g_flg[bg * 32];
        int prev;
        asm volatile("atom.acq_rel.gpu.global.add.s32 %0, [%1], 1;"
                     : "=r"(prev) : "l"(cnt) : "memory");
        if (prev == idx * kGrpCTA - 1) {
            int dummy;
            asm volatile("atom.release.gpu.global.exch.b32 %0, [%1], %2;"
                         : "=r"(dummy) : "l"(flg), "r"(idx) : "memory");
        } else {
            int v;
            do {
                asm volatile("ld.acquire.gpu.global.s32 %0, [%1];"
                             : "=r"(v) : "l"(flg) : "memory");
            } while (v < idx);
        }
    }
    __syncthreads();
}

// ---------------- persistent HMMA LSTM recurrence (R16, unchanged) --------------
__global__ void __launch_bounds__(256, 1)
lstm_recur_mma(const float* __restrict__ G,
               const __nv_bfloat16* __restrict__ WTh,
               const __nv_bfloat16* __restrict__ WTl,
               float* __restrict__ seqout,        // layer 1 only
               __nv_bfloat16* __restrict__ asOut, // layer 0 only
               float* __restrict__ hT, float* __restrict__ cT,
               const int tbase, const int gidx)
{
    __shared__ __align__(128) __nv_bfloat16 Ahs[4][16][kQRow];
    __shared__ __align__(16) float wgs[8 * 32 * 4];  // per-warp gate exchange
    __shared__ float Gs[16][68];
    __shared__ __align__(8) ull s_mbar[4];

    const int tid = threadIdx.x;
    const int cg  = blockIdx.x >> 2;
    const int bg  = blockIdx.x & 3;
    const int u0  = cg * 16;

    const int wid  = tid >> 5;
    const int lane = tid & 31;
    const int g8   = lane >> 2;
    const int tig  = lane & 3;

    uint32_t mbarQ[4], ahsQ[4], lmQ[4];
    const int lrow = ((lane >> 3) & 1) * 8 + (lane & 7);
    const int lcol = (lane >> 4) * 8;
#pragma unroll
    for (int q = 0; q < 4; q++) {
        mbarQ[q] = smem_u32(&s_mbar[q]);
        ahsQ[q]  = smem_u32(&Ahs[q][0][0]);
        lmQ[q]   = smem_u32(&Ahs[q][lrow][lcol]);
    }

    // Wh B-fragments: lane's B col (n_idx = g8) -> gate g8>>1, unit 2*wid+(g8&1)
    const int ng = (g8 >> 1) * kH + u0 + 2 * wid + (g8 & 1);
    uint32_t bfh[32][2], bfl[32][2];
#pragma unroll
    for (int ks = 0; ks < 32; ks++) {
        const int kk = ks * 16 + tig * 2;
        bfh[ks][0] = *(const uint32_t*)(WTh + (size_t)ng * 512 + kk);
        bfh[ks][1] = *(const uint32_t*)(WTh + (size_t)ng * 512 + kk + 8);
        bfl[ks][0] = *(const uint32_t*)(WTl + (size_t)ng * 512 + kk);
        bfl[ks][1] = *(const uint32_t*)(WTl + (size_t)ng * 512 + kk + 8);
    }

    const int pj = lane >> 4;
    const int pb = lane & 15;
    const int pu = 2 * wid + pj;
    const int bglob = bg * 16 + pb;

    const int qp = cg >> 3;
    const int cb = (cg & 7) * 16;

    g_hbf4[0][qp][bglob][cb + pu]       = __float2bfloat16_rn(0.f);
    g_hbf4[0][qp][bglob][128 + cb + pu] = __float2bfloat16_rn(0.f);
    float c_state = 0.f;
    if (tid < 4) mbar_init(mbarQ[tid], 1);

    gbar_rel(gidx, tid, bg);   // once per launch

    for (int t = 0; t < kT; t++) {
        const int cur = t & 1;

        // stage this step's input projections (coalesced)
        {
            const int b = tid >> 4, q = tid & 15;
            const int gg = q >> 2, f = q & 3;
            const float* src = G + ((size_t)(bg * 16 + b) * kT + t) * kG
                             + gg * kH + u0 + f * 4;
            float4 v = __ldcs((const float4*)src);
            *(float4*)&Gs[b][gg * 16 + f * 4] = v;
        }
        __syncthreads();   // Gs visible; fences wgs/Ahs reuse

        // warp 0: poll 32 producer flags; issue quarter copies as they're ready
        if (wid == 0) {
            const int* fp = &g_hflag[bg][lane * 32];
            const int want = tbase + t;
            unsigned issued = 0;
            do {
                int v;
                asm volatile("ld.acquire.gpu.global.s32 %0, [%1];"
                             : "=r"(v) : "l"(fp) : "memory");
                const unsigned m = __ballot_sync(0xFFFFFFFFu, v >= want);
#pragma unroll
                for (int q = 0; q < 4; q++) {
                    if (!(issued & (1u << q)) &&
                        ((m >> (8 * q)) & 0xFFu) == 0xFFu) {
                        if (lane == 8 * q) {
                            mbar_expect(mbarQ[q], kQBytes);
                            bulk_g2s(ahsQ[q], &g_hbf4[cur][q][bg * 16][0],
                                     kQBytes, mbarQ[q]);
                        }
                        issued |= 1u << q;
                    }
                }
            } while (issued != 0xFu);
        }

        // gate GEMM: 16x8 per warp, K=512, 3-term split, per-half chains
        float a0[4] = {0.f, 0.f, 0.f, 0.f};
        float a1[4] = {0.f, 0.f, 0.f, 0.f};
        float a2[4] = {0.f, 0.f, 0.f, 0.f};
        float b0[4] = {0.f, 0.f, 0.f, 0.f};
        float b1[4] = {0.f, 0.f, 0.f, 0.f};
        float b2[4] = {0.f, 0.f, 0.f, 0.f};
#pragma unroll
        for (int q = 0; q < 4; q++) {
            mbar_wait(mbarQ[q], t & 1);
            float* r0 = (q < 2) ? a0 : b0;
            float* r1 = (q < 2) ? a1 : b1;
            float* r2 = (q < 2) ? a2 : b2;
#pragma unroll
            for (int ks = 0; ks < 8; ks++) {
                uint32_t ah[4], al[4];
                ldmx4(ah, lmQ[q] + ks * 32);
                ldmx4(al, lmQ[q] + 256 + ks * 32);
                mma_bf16(r0, ah, bfh[q * 8 + ks]);
                mma_bf16(r1, al, bfh[q * 8 + ks]);
                mma_bf16(r2, ah, bfl[q * 8 + ks]);
            }
        }

        // warp-local gate exchange
        {
            float* wg = wgs + wid * 128;
            wg[(0 * 16 + g8) * 4 + tig]     = (a0[0] + a1[0]) + (a2[0] + b0[0]) + (b1[0] + b2[0]);
            wg[(1 * 16 + g8) * 4 + tig]     = (a0[1] + a1[1]) + (a2[1] + b0[1]) + (b1[1] + b2[1]);
            wg[(0 * 16 + g8 + 8) * 4 + tig] = (a0[2] + a1[2]) + (a2[2] + b0[2]) + (b1[2] + b2[2]);
            wg[(1 * 16 + g8 + 8) * 4 + tig] = (a0[3] + a1[3]) + (a2[3] + b0[3]) + (b1[3] + b2[3]);
        }
        __syncwarp();

        // pointwise: one (b,u) per thread
        float hval;
        {
            const float4 gv4 = *(const float4*)(wgs + wid * 128 + (pj * 16 + pb) * 4);
            const float iv = sigf(gv4.x + Gs[pb][0 * 16 + pu]);
            const float fv = sigf(gv4.y + Gs[pb][1 * 16 + pu]);
            const float gv = tanh_hw(gv4.z + Gs[pb][2 * 16 + pu]);
            const float ov = sigf(gv4.w + Gs[pb][3 * 16 + pu]);
            c_state = fv * c_state + iv * gv;
            hval = ov * tanh_hw(c_state);
        }
        const __nv_bfloat16 hh = __float2bfloat16_rn(hval);
        const __nv_bfloat16 hl = __float2bfloat16_rn(hval - __bfloat162float(hh));
        g_hbf4[cur ^ 1][qp][bglob][cb + pu]       = hh;
        g_hbf4[cur ^ 1][qp][bglob][128 + cb + pu] = hl;

        __syncthreads();   // all h stores happen-before the flag release
        if (tid == 0) {
            asm volatile("st.release.gpu.global.s32 [%0], %1;"
                         :: "l"(&g_hflag[bg][cg * 32]), "r"(tbase + t + 1)
                         : "memory");
        }

        // off-critical-path outputs (after flag)
        if (asOut) {
            const size_t m = (size_t)bglob * kT + t;
            asOut[m * 1024 + u0 + pu]       = hh;
            asOut[m * 1024 + 512 + u0 + pu] = hl;
        } else {
            seqout[((size_t)bglob * kT + t) * kH + u0 + pu] = hval;
        }
        if (t == kT - 1) {
            hT[(size_t)bglob * kH + u0 + pu] = hval;
            cT[(size_t)bglob * kH + u0 + pu] = c_state;
        }
    }
}

// ---------------- launch --------------------------------------------------------
extern "C" void kernel_launch(void* const* d_in, const int* in_sizes, int n_in,
                              void* d_out, int out_size)
{
    const float* x  = (const float*)d_in[0];
    const float* Wi = (const float*)d_in[1];
    const float* Wh = (const float*)d_in[2];
    const float* bi = (const float*)d_in[3];
    const float* bh = (const float*)d_in[4];

    float* out  = (float*)d_out;
    float* outs = out;
    float* hT   = out + (size_t)kB * kT * kH;
    float* cT   = hT + (size_t)2 * kB * kH;

    float* Gp;  cudaGetSymbolAddress((void**)&Gp,  g_G);
    __nv_bfloat16 *asp, *wih, *wil, *whh, *whl;
    cudaGetSymbolAddress((void**)&asp, g_As);
    cudaGetSymbolAddress((void**)&wih, g_WiTh);
    cudaGetSymbolAddress((void**)&wil, g_WiTl);
    cudaGetSymbolAddress((void**)&whh, g_WhTh);
    cudaGetSymbolAddress((void**)&whl, g_WhTl);

    cudaFuncSetAttribute(gemm_mma, cudaFuncAttributeMaxDynamicSharedMemorySize,
                         kGemmSmem);

    const dim3 gSplit(64, 16);
    const dim3 gGemm(kG / 256, kM / 128);   // (8, 128)

    // ---- layer 0
    split_pair<<<gSplit, 256>>>(Wi, wih, wil);
    split_pair<<<gSplit, 256>>>(Wh, whh, whl);
    split_x<<<kM * kH / 1024, 256>>>(x);          // also resets barrier state
    gemm_mma<<<gGemm, 256, kGemmSmem>>>(bi, bh, Gp);
    lstm_recur_mma<<<kCG * kBG, 256>>>(Gp, whh, whl,
                                       nullptr, asp, hT, cT, 0, 1);

    // ---- layer 1 (g_As now holds layer-0 h, already split)
    split_pair<<<gSplit, 256>>>(Wi + (size_t)kH * kG, wih, wil);
    split_pair<<<gSplit, 256>>>(Wh + (size_t)kH * kG, whh, whl);
    gemm_mma<<<gGemm, 256, kGemmSmem>>>(bi + kG, bh + kG, Gp);
    lstm_recur_mma<<<kCG * kBG, 256>>>(Gp, whh, whl,
                                       outs, nullptr,
                                       hT + (size_t)kB * kH,
                                       cT + (size_t)kB * kH, kT, 2);
}